// round 1
// baseline (speedup 1.0000x reference)
#include <cuda_runtime.h>
#include <math.h>

#define WINLEN 2048
#define HOPLEN 256
#define NBINS  1025
#define MAXT   8193
#define NLAG   511   // valid lags 1..511 (F//2 - 1 with F = 1025)

// Scratch (static device globals -- no allocation at runtime)
__device__ float g_mag[(size_t)MAXT * NBINS];
__device__ float g_f0[MAXT];

// ---------------------------------------------------------------------------
// Kernel 1: STFT magnitude. One block (256 threads) per frame.
// Reflect-padded, periodic-Hann-windowed 2048-pt FFT via Stockham (autosort).
// ---------------------------------------------------------------------------
__global__ void __launch_bounds__(256) stft_kernel(const float* __restrict__ audio,
                                                   int n) {
    const int t   = blockIdx.x;
    const int tid = threadIdx.x;

    __shared__ float2 bufA[WINLEN];
    __shared__ float2 bufB[WINLEN];
    __shared__ float2 tw[WINLEN / 2];

    // Twiddle table: tw[p] = exp(-2*pi*i * p / 2048)
    #pragma unroll
    for (int p = tid; p < WINLEN / 2; p += 256) {
        float s, c;
        sincospif(-(float)p * (2.0f / (float)WINLEN), &s, &c);
        tw[p] = make_float2(c, s);
    }

    // Load frame with reflect padding (pad = 1024 each side) + periodic Hann
    const int start = t * HOPLEN - WINLEN / 2;
    #pragma unroll
    for (int j = tid; j < WINLEN; j += 256) {
        int ix = start + j;
        if (ix < 0)       ix = -ix;
        else if (ix >= n) ix = 2 * n - 2 - ix;
        float w = 0.5f - 0.5f * cospif((float)j * (2.0f / (float)WINLEN));
        bufA[j] = make_float2(audio[ix] * w, 0.0f);
    }
    __syncthreads();

    // Stockham DIF FFT, 11 stages, ping-pong bufA <-> bufB, natural-order output
    float2* src = bufA;
    float2* dst = bufB;
    int s = 1;
    #pragma unroll 1
    for (int stage = 0; stage < 11; ++stage) {
        #pragma unroll
        for (int b = tid; b < WINLEN / 2; b += 256) {
            int    q  = b & (s - 1);          // b % s
            float2 a  = src[b];
            float2 bb = src[b + WINLEN / 2];
            float2 w  = tw[b - q];            // tw[(b/s)*s] = exp(-2pi i p / nn)
            float2 sum = make_float2(a.x + bb.x, a.y + bb.y);
            float2 dif = make_float2(a.x - bb.x, a.y - bb.y);
            float2 dw  = make_float2(dif.x * w.x - dif.y * w.y,
                                     dif.x * w.y + dif.y * w.x);
            int d0 = 2 * b - q;
            dst[d0]     = sum;
            dst[d0 + s] = dw;
        }
        __syncthreads();
        float2* tmp = src; src = dst; dst = tmp;
        s <<= 1;
    }
    // After 11 stages result sits in `src`

    float* mg = g_mag + (size_t)t * NBINS;
    #pragma unroll
    for (int k = tid; k < NBINS; k += 256) {
        float2 v = src[k];
        mg[k] = sqrtf(v.x * v.x + v.y * v.y);
    }
}

// ---------------------------------------------------------------------------
// Kernel 2: per-frame autocorrelation with chunked early exit + peak test.
// One block (256 threads) per frame; 4 threads per lag, 64 lags per chunk.
// f0[t] = 50 iff any strict interior local max exists in ac[1..] (reference
// semantics: peaks at lag L in [2,1023], with ac zeroed outside [1,511]).
// ---------------------------------------------------------------------------
__global__ void __launch_bounds__(256) ac_kernel(int T) {
    const int t   = blockIdx.x;
    const int tid = threadIdx.x;

    __shared__ float m[NBINS];
    __shared__ float ac[NLAG + 2];   // ac[1..511], ac[512] = 0 sentinel
    __shared__ int   found;

    const float* mg = g_mag + (size_t)t * NBINS;
    #pragma unroll
    for (int i = tid; i < NBINS; i += 256) m[i] = mg[i];
    if (tid == 0) { found = 0; ac[NLAG + 1] = 0.0f; }
    __syncthreads();

    #pragma unroll 1
    for (int L0 = 1; L0 <= NLAG; L0 += 64) {
        const int lag  = L0 + (tid >> 2);
        const int part = tid & 3;
        float sum = 0.0f;
        if (lag <= NLAG) {
            const int kmax = NBINS - lag;
            #pragma unroll 4
            for (int k = part; k < kmax; k += 4)
                sum += m[k] * m[k + lag];
        }
        // reduce the 4 partials within each quad (same warp, adjacent lanes)
        sum += __shfl_xor_sync(0xffffffffu, sum, 1);
        sum += __shfl_xor_sync(0xffffffffu, sum, 2);
        if (part == 0 && lag <= NLAG) ac[lag] = sum;
        __syncthreads();

        const int hi      = min(L0 + 63, NLAG);
        const int checkHi = (hi == NLAG) ? NLAG : (hi - 1);  // need ac[L+1]
        for (int L = 2 + tid; L <= checkHi; L += 256) {
            if (ac[L] > ac[L - 1] && ac[L] > ac[L + 1]) found = 1;
        }
        __syncthreads();
        if (found) break;   // uniform: `found` stable after barrier
    }

    if (tid == 0) g_f0[t] = found ? 50.0f : 0.0f;
}

// ---------------------------------------------------------------------------
// Kernel 3: median-of-5 smoothing with edge-clamped padding.
// ---------------------------------------------------------------------------
__global__ void median_kernel(float* __restrict__ out, int T) {
    int t = blockIdx.x * blockDim.x + threadIdx.x;
    if (t >= T) return;
    float v[5];
    #pragma unroll
    for (int i = 0; i < 5; ++i) {
        int j = t - 2 + i;
        j = max(0, min(T - 1, j));
        v[i] = g_f0[j];
    }
    #pragma unroll
    for (int i = 0; i < 4; ++i)
        #pragma unroll
        for (int j = 0; j < 4 - i; ++j)
            if (v[j] > v[j + 1]) { float tmp = v[j]; v[j] = v[j + 1]; v[j + 1] = tmp; }
    out[t] = v[2];
}

// ---------------------------------------------------------------------------
extern "C" void kernel_launch(void* const* d_in, const int* in_sizes, int n_in,
                              void* d_out, int out_size) {
    const float* audio = (const float*)d_in[0];
    const int n = in_sizes[0];
    const int T = n / HOPLEN + 1;   // 8193 for n = 2097152
    float* out = (float*)d_out;

    stft_kernel<<<T, 256>>>(audio, n);
    ac_kernel<<<T, 256>>>(T);
    median_kernel<<<(T + 255) / 256, 256>>>(out, T);
}

// round 2
// speedup vs baseline: 2.2432x; 2.2432x over previous
#include <cuda_runtime.h>
#include <math.h>

#define HOPLEN 256
#define NBINS  1025        // rfft bins of 2048-pt FFT
#define MAXT   8193
#define NLAG   511         // valid lags 1..511
#define NC     1024        // complex FFT length (real-packed)

__device__ float g_f0[MAXT];

__device__ __forceinline__ float2 cmul(float2 a, float2 b) {
    return make_float2(a.x * b.x - a.y * b.y, a.x * b.y + a.y * b.x);
}

// ---------------------------------------------------------------------------
// Fused kernel: STFT magnitude (real-packed radix-4 Stockham FFT) + spectral
// autocorrelation with chunked early exit. One block (256 threads) per frame.
// ---------------------------------------------------------------------------
__global__ void __launch_bounds__(256) fused_kernel(const float* __restrict__ audio,
                                                    int n) {
    const int t   = blockIdx.x;
    const int tid = threadIdx.x;

    __shared__ __align__(16) float2 bufA[NC];
    __shared__ __align__(16) float2 bufB[NC];
    __shared__ __align__(16) float  ac[516];
    __shared__ int found;

    // ---- load frame: reflect pad, periodic Hann, pack even+i*odd ----------
    const int start = t * HOPLEN - 1024;
    #pragma unroll
    for (int jj = tid; jj < NC; jj += 256) {
        int j0 = 2 * jj, j1 = 2 * jj + 1;
        int i0 = start + j0, i1 = start + j1;
        if (i0 < 0) i0 = -i0; else if (i0 >= n) i0 = 2 * n - 2 - i0;
        if (i1 < 0) i1 = -i1; else if (i1 >= n) i1 = 2 * n - 2 - i1;
        float w0 = 0.5f - 0.5f * cospif((float)j0 * (1.0f / 1024.0f));
        float w1 = 0.5f - 0.5f * cospif((float)j1 * (1.0f / 1024.0f));
        bufA[jj] = make_float2(audio[i0] * w0, audio[i1] * w1);
    }
    if (tid == 0) { found = 0; ac[512] = 0.0f; }
    __syncthreads();

    // ---- 1024-pt forward FFT: 5 radix-4 Stockham stages (A->B->A->B->A->B)
    float2* src = bufA;
    float2* dst = bufB;
    int s = 1;
    #pragma unroll
    for (int stage = 0; stage < 5; ++stage) {
        const int b = tid;                 // one butterfly per thread
        const int q = b & (s - 1);
        const int p = b - q;               // multiple of s
        float2 a0 = src[b];
        float2 a1 = src[b + 256];
        float2 a2 = src[b + 512];
        float2 a3 = src[b + 768];
        float2 s02 = make_float2(a0.x + a2.x, a0.y + a2.y);
        float2 d02 = make_float2(a0.x - a2.x, a0.y - a2.y);
        float2 s13 = make_float2(a1.x + a3.x, a1.y + a3.y);
        float2 d13 = make_float2(a1.x - a3.x, a1.y - a3.y);
        float2 y0 = make_float2(s02.x + s13.x, s02.y + s13.y);
        float2 y2 = make_float2(s02.x - s13.x, s02.y - s13.y);
        float2 y1 = make_float2(d02.x + d13.y, d02.y - d13.x);  // d02 - i*d13
        float2 y3 = make_float2(d02.x - d13.y, d02.y + d13.x);  // d02 + i*d13
        float si, co;
        sincospif(-(float)p * (1.0f / 512.0f), &si, &co);
        float2 W1 = make_float2(co, si);
        sincospif(-(float)p * (1.0f / 256.0f), &si, &co);
        float2 W2 = make_float2(co, si);
        sincospif(-(float)(3 * p) * (1.0f / 512.0f), &si, &co);
        float2 W3 = make_float2(co, si);
        int base = 4 * p + q;
        dst[base]         = y0;
        dst[base + s]     = cmul(W1, y1);
        dst[base + 2 * s] = cmul(W2, y2);
        dst[base + 3 * s] = cmul(W3, y3);
        __syncthreads();
        float2* tmp = src; src = dst; dst = tmp;
        s <<= 2;
    }
    // after 5 stages, Z lives in bufB (src); bufA is dead -> reuse as mag

    float* m = (float*)bufA;               // 2048 floats available
    const float2* Z = src;                 // == bufB

    // ---- untangle rfft of 2048 real samples, write magnitude into m --------
    #pragma unroll
    for (int k = tid; k < NBINS; k += 256) {
        float2 Zk  = Z[k & (NC - 1)];
        float2 Zmk = Z[(NC - k) & (NC - 1)];
        float Er = 0.5f * (Zk.x + Zmk.x);
        float Ei = 0.5f * (Zk.y - Zmk.y);
        float u  = Zk.x - Zmk.x;
        float v  = Zk.y + Zmk.y;
        float sn, cs;
        sincospif((float)k * (1.0f / 1024.0f), &sn, &cs);   // W = (cs, -sn)
        // X = E + 0.5*W*(v - i*u)
        float Xr = Er + 0.5f * (cs * v - sn * u);
        float Xi = Ei + 0.5f * (-sn * v - cs * u);
        m[k] = sqrtf(Xr * Xr + Xi * Xi);
    }
    // zero-pad m so autocorrelation needs no per-lag bounds (max idx 1539)
    for (int i = NBINS + tid; i < 1552; i += 256) m[i] = 0.0f;
    __syncthreads();

    // ---- autocorrelation: chunks of 64 lags, 4 lags/thread, early exit -----
    // thread layout: lag group g = tid>>4 (4 lags), k partition = tid&15
    const int g     = tid >> 4;
    const int kpart = tid & 15;
    int loLag = 2;

    #pragma unroll 1
    for (int Cbase = 0; Cbase <= 448; Cbase += 64) {
        const int L = Cbase + 4 * g;       // 16-byte aligned lag base
        float4 acc = make_float4(0.f, 0.f, 0.f, 0.f);
        #pragma unroll 4
        for (int k = 4 * kpart; k < 1028; k += 64) {
            float4 a  = *(const float4*)(m + k);
            float4 b0 = *(const float4*)(m + k + L);
            float4 b1 = *(const float4*)(m + k + L + 4);
            acc.x += a.x * b0.x + a.y * b0.y + a.z * b0.z + a.w * b0.w;
            acc.y += a.x * b0.y + a.y * b0.z + a.z * b0.w + a.w * b1.x;
            acc.z += a.x * b0.z + a.y * b0.w + a.z * b1.x + a.w * b1.y;
            acc.w += a.x * b0.w + a.y * b1.x + a.z * b1.y + a.w * b1.z;
        }
        // reduce 16 k-partitions (lanes sharing g live in one 16-lane half)
        #pragma unroll
        for (int mask = 1; mask < 16; mask <<= 1) {
            acc.x += __shfl_xor_sync(0xffffffffu, acc.x, mask);
            acc.y += __shfl_xor_sync(0xffffffffu, acc.y, mask);
            acc.z += __shfl_xor_sync(0xffffffffu, acc.z, mask);
            acc.w += __shfl_xor_sync(0xffffffffu, acc.w, mask);
        }
        if (kpart == 0) *(float4*)(ac + L) = acc;
        __syncthreads();

        const int hiLag   = Cbase + 63;
        const int checkHi = (hiLag >= NLAG) ? NLAG : (hiLag - 1);
        for (int Lc = loLag + tid; Lc <= checkHi; Lc += 256) {
            if (ac[Lc] > ac[Lc - 1] && ac[Lc] > ac[Lc + 1]) found = 1;
        }
        loLag = checkHi + 1;
        __syncthreads();
        if (found) break;                   // uniform after barrier
    }

    if (tid == 0) g_f0[t] = found ? 50.0f : 0.0f;
}

// ---------------------------------------------------------------------------
// Median-of-5 smoothing with edge-clamped padding.
// ---------------------------------------------------------------------------
__global__ void median_kernel(float* __restrict__ out, int T) {
    int t = blockIdx.x * blockDim.x + threadIdx.x;
    if (t >= T) return;
    float v[5];
    #pragma unroll
    for (int i = 0; i < 5; ++i) {
        int j = t - 2 + i;
        j = max(0, min(T - 1, j));
        v[i] = g_f0[j];
    }
    #pragma unroll
    for (int i = 0; i < 4; ++i)
        #pragma unroll
        for (int j = 0; j < 4 - i; ++j)
            if (v[j] > v[j + 1]) { float tmp = v[j]; v[j] = v[j + 1]; v[j + 1] = tmp; }
    out[t] = v[2];
}

// ---------------------------------------------------------------------------
extern "C" void kernel_launch(void* const* d_in, const int* in_sizes, int n_in,
                              void* d_out, int out_size) {
    const float* audio = (const float*)d_in[0];
    const int n = in_sizes[0];
    const int T = n / HOPLEN + 1;
    float* out = (float*)d_out;

    fused_kernel<<<T, 256>>>(audio, n);
    median_kernel<<<(T + 255) / 256, 256>>>(out, T);
}

// round 3
// speedup vs baseline: 2.5943x; 1.1565x over previous
#include <cuda_runtime.h>
#include <math.h>

#define HOPLEN 256
#define NBINS  1025        // rfft bins of 2048-pt FFT
#define MAXT   8193
#define NLAG   511         // valid lags 1..511
#define NC     1024        // complex FFT length (real-packed)

__device__ float  g_f0[MAXT];
__device__ float2 g_twm[2 * NC];   // twm[j] = exp(-i*pi*j/1024), j in [0,2048)

__device__ __forceinline__ float2 cmul(float2 a, float2 b) {
    return make_float2(a.x * b.x - a.y * b.y, a.x * b.y + a.y * b.x);
}

// ---------------------------------------------------------------------------
// Init: master twiddle table (bit-identical to in-kernel sincospif values).
// ---------------------------------------------------------------------------
__global__ void twiddle_init_kernel() {
    int j = blockIdx.x * blockDim.x + threadIdx.x;
    if (j < 2 * NC) {
        float s, c;
        sincospif(-(float)j * (1.0f / 1024.0f), &s, &c);
        g_twm[j] = make_float2(c, s);
    }
}

// ---------------------------------------------------------------------------
// Fused kernel: STFT magnitude (real-packed radix-4 Stockham FFT, table
// twiddles) + spectral autocorrelation with chunked early exit.
// One block (256 threads) per frame.
// ---------------------------------------------------------------------------
__global__ void __launch_bounds__(256) fused_kernel(const float* __restrict__ audio,
                                                    int n) {
    const int t   = blockIdx.x;
    const int tid = threadIdx.x;

    __shared__ __align__(16) float2 bufA[NC];
    __shared__ __align__(16) float2 bufB[NC];
    __shared__ __align__(16) float  ac[516];
    __shared__ int found;

    const float2* __restrict__ twm = g_twm;

    // ---- load frame: reflect pad, Hann (from table), pack even+i*odd -------
    const int start = t * HOPLEN - 1024;
    #pragma unroll
    for (int jj = tid; jj < NC; jj += 256) {
        int j0 = 2 * jj, j1 = 2 * jj + 1;
        int i0 = start + j0, i1 = start + j1;
        if (i0 < 0) i0 = -i0; else if (i0 >= n) i0 = 2 * n - 2 - i0;
        if (i1 < 0) i1 = -i1; else if (i1 >= n) i1 = 2 * n - 2 - i1;
        float4 tv = *(const float4*)(twm + j0);          // (twm[j0], twm[j1])
        float w0 = 0.5f - 0.5f * tv.x;                   // hann[j0]
        float w1 = 0.5f - 0.5f * tv.z;                   // hann[j1]
        bufA[jj] = make_float2(audio[i0] * w0, audio[i1] * w1);
    }
    if (tid == 0) { found = 0; ac[512] = 0.0f; }
    __syncthreads();

    // ---- 1024-pt forward FFT: 5 radix-4 Stockham stages ---------------------
    float2* src = bufA;
    float2* dst = bufB;
    int s = 1;
    #pragma unroll
    for (int stage = 0; stage < 5; ++stage) {
        const int b = tid;                 // one butterfly per thread
        const int q = b & (s - 1);
        const int p = b - q;               // multiple of s
        float2 a0 = src[b];
        float2 a1 = src[b + 256];
        float2 a2 = src[b + 512];
        float2 a3 = src[b + 768];
        float2 s02 = make_float2(a0.x + a2.x, a0.y + a2.y);
        float2 d02 = make_float2(a0.x - a2.x, a0.y - a2.y);
        float2 s13 = make_float2(a1.x + a3.x, a1.y + a3.y);
        float2 d13 = make_float2(a1.x - a3.x, a1.y - a3.y);
        float2 y0 = make_float2(s02.x + s13.x, s02.y + s13.y);
        float2 y2 = make_float2(s02.x - s13.x, s02.y - s13.y);
        float2 y1 = make_float2(d02.x + d13.y, d02.y - d13.x);  // d02 - i*d13
        float2 y3 = make_float2(d02.x - d13.y, d02.y + d13.x);  // d02 + i*d13
        float2 W1 = twm[2 * p];            // exp(-i*pi*p/512)
        float2 W2 = twm[4 * p];            // exp(-i*pi*p/256)
        float2 W3 = twm[6 * p];            // exp(-i*pi*3p/512)
        int base = 4 * p + q;
        dst[base]         = y0;
        dst[base + s]     = cmul(W1, y1);
        dst[base + 2 * s] = cmul(W2, y2);
        dst[base + 3 * s] = cmul(W3, y3);
        __syncthreads();
        float2* tmp = src; src = dst; dst = tmp;
        s <<= 2;
    }
    // after 5 stages, Z lives in src (== bufB); bufA is dead -> reuse as mag

    float* m = (float*)bufA;               // 2048 floats available
    const float2* Z = src;

    // ---- untangle rfft of 2048 real samples, magnitude into m --------------
    #pragma unroll
    for (int k = tid; k < NBINS; k += 256) {
        float2 Zk  = Z[k & (NC - 1)];
        float2 Zmk = Z[(NC - k) & (NC - 1)];
        float Er = 0.5f * (Zk.x + Zmk.x);
        float Ei = 0.5f * (Zk.y - Zmk.y);
        float u  = Zk.x - Zmk.x;
        float v  = Zk.y + Zmk.y;
        float2 W = twm[k];                 // (cos, -sin) of pi*k/1024
        float Xr = Er + 0.5f * (W.x * v + W.y * u);
        float Xi = Ei + 0.5f * (W.y * v - W.x * u);
        m[k] = sqrtf(Xr * Xr + Xi * Xi);
    }
    // zero-pad so the autocorrelation needs no bounds checks anywhere
    for (int i = NBINS + tid; i < 2048; i += 256) m[i] = 0.0f;
    __syncthreads();

    // ---- autocorrelation: chunks of 32 lags, warp = 4 lags, early exit ------
    const int w    = tid >> 5;             // warp id: lag group
    const int lane = tid & 31;             // k partition
    int loLag = 2;

    #pragma unroll 1
    for (int C = 0; C <= 480; C += 32) {
        const int L = C + 4 * w;           // this warp's 4 lags: L..L+3
        float4 acc = make_float4(0.f, 0.f, 0.f, 0.f);
        #pragma unroll 3
        for (int i = 0; i < 9; ++i) {
            int k = 4 * lane + 128 * i;    // covers all k multiples of 4 <= 1024
            float4 a  = *(const float4*)(m + k);
            float4 b0 = *(const float4*)(m + k + L);
            float4 b1 = *(const float4*)(m + k + L + 4);
            acc.x += a.x * b0.x + a.y * b0.y + a.z * b0.z + a.w * b0.w;
            acc.y += a.x * b0.y + a.y * b0.z + a.z * b0.w + a.w * b1.x;
            acc.z += a.x * b0.z + a.y * b0.w + a.z * b1.x + a.w * b1.y;
            acc.w += a.x * b0.w + a.y * b1.x + a.z * b1.y + a.w * b1.z;
        }
        #pragma unroll
        for (int mask = 1; mask < 32; mask <<= 1) {
            acc.x += __shfl_xor_sync(0xffffffffu, acc.x, mask);
            acc.y += __shfl_xor_sync(0xffffffffu, acc.y, mask);
            acc.z += __shfl_xor_sync(0xffffffffu, acc.z, mask);
            acc.w += __shfl_xor_sync(0xffffffffu, acc.w, mask);
        }
        if (lane == 0) *(float4*)(ac + L) = acc;
        __syncthreads();

        const int hiLag   = C + 31;
        const int checkHi = (hiLag >= NLAG) ? NLAG : (hiLag - 1);
        for (int Lc = loLag + tid; Lc <= checkHi; Lc += 256) {
            if (ac[Lc] > ac[Lc - 1] && ac[Lc] > ac[Lc + 1]) found = 1;
        }
        loLag = checkHi + 1;
        __syncthreads();
        if (found) break;                  // uniform after barrier
    }

    if (tid == 0) g_f0[t] = found ? 50.0f : 0.0f;
}

// ---------------------------------------------------------------------------
// Median-of-5 smoothing with edge-clamped padding.
// ---------------------------------------------------------------------------
__global__ void median_kernel(float* __restrict__ out, int T) {
    int t = blockIdx.x * blockDim.x + threadIdx.x;
    if (t >= T) return;
    float v[5];
    #pragma unroll
    for (int i = 0; i < 5; ++i) {
        int j = t - 2 + i;
        j = max(0, min(T - 1, j));
        v[i] = g_f0[j];
    }
    #pragma unroll
    for (int i = 0; i < 4; ++i)
        #pragma unroll
        for (int j = 0; j < 4 - i; ++j)
            if (v[j] > v[j + 1]) { float tmp = v[j]; v[j] = v[j + 1]; v[j + 1] = tmp; }
    out[t] = v[2];
}

// ---------------------------------------------------------------------------
extern "C" void kernel_launch(void* const* d_in, const int* in_sizes, int n_in,
                              void* d_out, int out_size) {
    const float* audio = (const float*)d_in[0];
    const int n = in_sizes[0];
    const int T = n / HOPLEN + 1;
    float* out = (float*)d_out;

    twiddle_init_kernel<<<8, 256>>>();
    fused_kernel<<<T, 256>>>(audio, n);
    median_kernel<<<(T + 255) / 256, 256>>>(out, T);
}

// round 4
// speedup vs baseline: 3.0720x; 1.1841x over previous
#include <cuda_runtime.h>
#include <math.h>

#define HOPLEN 256
#define NBINS  1025
#define MAXT   8193
#define NLAG   511
#define NC     1024

__device__ float  g_f0[MAXT];
__device__ float2 g_twm[2 * NC];   // twm[j] = exp(-i*pi*j/1024)

__device__ __forceinline__ float2 cmul(float2 a, float2 b) {
    return make_float2(a.x * b.x - a.y * b.y, a.x * b.y + a.y * b.x);
}
// low-bit XOR swizzle for bufB (kills pass-1 write conflicts)
__device__ __forceinline__ int swz(int i) { return i ^ ((i >> 4) & 15); }

__global__ void twiddle_init_kernel() {
    int j = blockIdx.x * blockDim.x + threadIdx.x;
    if (j < 2 * NC) {
        float s, c;
        sincospif(-(float)j * (1.0f / 1024.0f), &s, &c);
        g_twm[j] = make_float2(c, s);
    }
}

// Merged pair of radix-4 Stockham stages (spans S and 4S) for thread c in
// [0,64). Stage-A butterflies {c+64j}; stage-B butterflies {4c-3q+S*rh},
// intermediate kept in registers. SWIN/SWOUT apply the bufB swizzle.
template<int S, bool SWIN, bool SWOUT>
__device__ __forceinline__ void fft_pass16(const float2* __restrict__ src,
                                           float2* __restrict__ dst,
                                           const float2* __restrict__ twm,
                                           int c) {
    const int q = c & (S - 1);
    float2 t[4][4];
    #pragma unroll
    for (int j = 0; j < 4; ++j) {
        const int b = c + 64 * j;
        float2 a0 = src[SWIN ? swz(b)       : (b)];
        float2 a1 = src[SWIN ? swz(b + 256) : (b + 256)];
        float2 a2 = src[SWIN ? swz(b + 512) : (b + 512)];
        float2 a3 = src[SWIN ? swz(b + 768) : (b + 768)];
        float2 s02 = make_float2(a0.x + a2.x, a0.y + a2.y);
        float2 d02 = make_float2(a0.x - a2.x, a0.y - a2.y);
        float2 s13 = make_float2(a1.x + a3.x, a1.y + a3.y);
        float2 d13 = make_float2(a1.x - a3.x, a1.y - a3.y);
        float2 y0 = make_float2(s02.x + s13.x, s02.y + s13.y);
        float2 y2 = make_float2(s02.x - s13.x, s02.y - s13.y);
        float2 y1 = make_float2(d02.x + d13.y, d02.y - d13.x);
        float2 y3 = make_float2(d02.x - d13.y, d02.y + d13.x);
        const int p = b - q;
        t[j][0] = y0;
        t[j][1] = cmul(twm[2 * p], y1);
        t[j][2] = cmul(twm[4 * p], y2);
        t[j][3] = cmul(twm[6 * p], y3);
    }
    #pragma unroll
    for (int rh = 0; rh < 4; ++rh) {
        float2 a0 = t[0][rh], a1 = t[1][rh], a2 = t[2][rh], a3 = t[3][rh];
        const int b4 = 4 * c - 3 * q + S * rh;
        const int q4 = b4 & (4 * S - 1);
        const int p4 = b4 - q4;
        float2 s02 = make_float2(a0.x + a2.x, a0.y + a2.y);
        float2 d02 = make_float2(a0.x - a2.x, a0.y - a2.y);
        float2 s13 = make_float2(a1.x + a3.x, a1.y + a3.y);
        float2 d13 = make_float2(a1.x - a3.x, a1.y - a3.y);
        float2 y0 = make_float2(s02.x + s13.x, s02.y + s13.y);
        float2 y2 = make_float2(s02.x - s13.x, s02.y - s13.y);
        float2 y1 = make_float2(d02.x + d13.y, d02.y - d13.x);
        float2 y3 = make_float2(d02.x - d13.y, d02.y + d13.x);
        const int base = 4 * p4 + q4;
        dst[SWOUT ? swz(base)             : (base)]             = y0;
        dst[SWOUT ? swz(base + 4 * S)     : (base + 4 * S)]     = cmul(twm[2 * p4], y1);
        dst[SWOUT ? swz(base + 8 * S)     : (base + 8 * S)]     = cmul(twm[4 * p4], y2);
        dst[SWOUT ? swz(base + 12 * S)    : (base + 12 * S)]    = cmul(twm[6 * p4], y3);
    }
}

// ---------------------------------------------------------------------------
// Fused: STFT magnitude (real-packed 1024-pt FFT: two merged radix-16 passes
// + one radix-4 pass) + autocorrelation (16-lag chunks, early exit).
// One block (256 threads) per frame.
// ---------------------------------------------------------------------------
__global__ void __launch_bounds__(256) fused_kernel(const float* __restrict__ audio,
                                                    int n) {
    const int t   = blockIdx.x;
    const int tid = threadIdx.x;

    __shared__ __align__(16) float2 bufA[NC];
    __shared__ __align__(16) float2 bufB[NC];
    __shared__ __align__(16) float  ac[516];
    __shared__ __align__(16) float  part[8][4];
    __shared__ int found;

    const float2* __restrict__ twm = g_twm;

    // ---- load: reflect pad, Hann from table, pack even + i*odd -------------
    const int start = t * HOPLEN - 1024;
    #pragma unroll
    for (int jj = tid; jj < NC; jj += 256) {
        int j0 = 2 * jj, j1 = 2 * jj + 1;
        int i0 = start + j0, i1 = start + j1;
        if (i0 < 0) i0 = -i0; else if (i0 >= n) i0 = 2 * n - 2 - i0;
        if (i1 < 0) i1 = -i1; else if (i1 >= n) i1 = 2 * n - 2 - i1;
        float4 tv = *(const float4*)(twm + j0);
        float w0 = 0.5f - 0.5f * tv.x;
        float w1 = 0.5f - 0.5f * tv.z;
        bufA[jj] = make_float2(audio[i0] * w0, audio[i1] * w1);
    }
    if (tid == 0) { found = 0; ac[512] = 0.0f; }
    __syncthreads();

    // ---- FFT: pass1 (s=1,4) A->B(swz); pass2 (s=16,64) B(swz)->A;
    //           pass3 (s=256, twiddle-free) A->B
    if (tid < 64) fft_pass16<1, false, true>(bufA, bufB, twm, tid);
    __syncthreads();
    if (tid < 64) fft_pass16<16, true, false>(bufB, bufA, twm, tid);
    __syncthreads();
    {
        const int b = tid;
        float2 a0 = bufA[b], a1 = bufA[b + 256], a2 = bufA[b + 512], a3 = bufA[b + 768];
        float2 s02 = make_float2(a0.x + a2.x, a0.y + a2.y);
        float2 d02 = make_float2(a0.x - a2.x, a0.y - a2.y);
        float2 s13 = make_float2(a1.x + a3.x, a1.y + a3.y);
        float2 d13 = make_float2(a1.x - a3.x, a1.y - a3.y);
        bufB[b]       = make_float2(s02.x + s13.x, s02.y + s13.y);
        bufB[b + 256] = make_float2(d02.x + d13.y, d02.y - d13.x);
        bufB[b + 512] = make_float2(s02.x - s13.x, s02.y - s13.y);
        bufB[b + 768] = make_float2(d02.x - d13.y, d02.y + d13.x);
    }
    __syncthreads();

    // ---- untangle rfft of 2048 real samples, magnitude into m (= bufA) -----
    float* m = (float*)bufA;
    const float2* Z = bufB;
    #pragma unroll
    for (int k = tid; k < NBINS; k += 256) {
        float2 Zk  = Z[k & (NC - 1)];
        float2 Zmk = Z[(NC - k) & (NC - 1)];
        float Er = 0.5f * (Zk.x + Zmk.x);
        float Ei = 0.5f * (Zk.y - Zmk.y);
        float u  = Zk.x - Zmk.x;
        float v  = Zk.y + Zmk.y;
        float2 W = twm[k];
        float Xr = Er + 0.5f * (W.x * v + W.y * u);
        float Xi = Ei + 0.5f * (W.y * v - W.x * u);
        m[k] = sqrtf(Xr * Xr + Xi * Xi);
    }
    for (int i = NBINS + tid; i < 2048; i += 256) m[i] = 0.0f;
    __syncthreads();

    // ---- autocorrelation: 16-lag chunks, 2 warps per 4-lag group ------------
    const int w    = tid >> 5;
    const int lane = tid & 31;
    const int g    = w >> 1;            // lag group 0..3 (4 lags each)
    const int half = w & 1;             // k-space half
    const int kbase = 4 * lane + 128 * half;

    // cache the 'a' vector (constant across chunks) in registers
    float4 areg[5];
    #pragma unroll
    for (int i = 0; i < 5; ++i)
        areg[i] = *(const float4*)(m + kbase + 256 * i);

    int loLag = 2;
    #pragma unroll 1
    for (int C = 0; C <= 496; C += 16) {
        const int L = C + 4 * g;
        float4 acc = make_float4(0.f, 0.f, 0.f, 0.f);
        #pragma unroll
        for (int i = 0; i < 5; ++i) {
            const float4 a = areg[i];
            const float* bp = m + kbase + 256 * i + L;
            float4 b0 = *(const float4*)bp;
            float4 b1 = *(const float4*)(bp + 4);
            acc.x += a.x * b0.x + a.y * b0.y + a.z * b0.z + a.w * b0.w;
            acc.y += a.x * b0.y + a.y * b0.z + a.z * b0.w + a.w * b1.x;
            acc.z += a.x * b0.z + a.y * b0.w + a.z * b1.x + a.w * b1.y;
            acc.w += a.x * b0.w + a.y * b1.x + a.z * b1.y + a.w * b1.z;
        }
        #pragma unroll
        for (int mask = 1; mask < 32; mask <<= 1) {
            acc.x += __shfl_xor_sync(0xffffffffu, acc.x, mask);
            acc.y += __shfl_xor_sync(0xffffffffu, acc.y, mask);
            acc.z += __shfl_xor_sync(0xffffffffu, acc.z, mask);
            acc.w += __shfl_xor_sync(0xffffffffu, acc.w, mask);
        }
        if (lane == 0) *(float4*)&part[w][0] = acc;
        __syncthreads();

        const int hiLag   = C + 15;
        const int checkHi = (hiLag >= NLAG) ? NLAG : (hiLag - 1);
        if (tid < 16) {
            // store combined ac for this chunk (needed by later chunks)
            ac[C + tid] = part[2 * (tid >> 2)][tid & 3] + part[2 * (tid >> 2) + 1][tid & 3];
        }
        if (tid < 32) {
            const int lam = loLag + tid;
            if (lam <= checkHi) {
                float vm, v0, vp;
                {
                    unsigned d = (unsigned)(lam - 1 - C);
                    vm = (d < 16u) ? (part[2 * (d >> 2)][d & 3] + part[2 * (d >> 2) + 1][d & 3]) : ac[lam - 1];
                }
                {
                    unsigned d = (unsigned)(lam - C);
                    v0 = (d < 16u) ? (part[2 * (d >> 2)][d & 3] + part[2 * (d >> 2) + 1][d & 3]) : ac[lam];
                }
                {
                    unsigned d = (unsigned)(lam + 1 - C);
                    vp = (d < 16u) ? (part[2 * (d >> 2)][d & 3] + part[2 * (d >> 2) + 1][d & 3]) : ac[lam + 1];
                }
                if (v0 > vm && v0 > vp) found = 1;
            }
        }
        loLag = checkHi + 1;
        __syncthreads();
        if (found) break;               // uniform after barrier
    }

    if (tid == 0) g_f0[t] = found ? 50.0f : 0.0f;
}

// ---------------------------------------------------------------------------
__global__ void median_kernel(float* __restrict__ out, int T) {
    int t = blockIdx.x * blockDim.x + threadIdx.x;
    if (t >= T) return;
    float v[5];
    #pragma unroll
    for (int i = 0; i < 5; ++i) {
        int j = t - 2 + i;
        j = max(0, min(T - 1, j));
        v[i] = g_f0[j];
    }
    #pragma unroll
    for (int i = 0; i < 4; ++i)
        #pragma unroll
        for (int j = 0; j < 4 - i; ++j)
            if (v[j] > v[j + 1]) { float tmp = v[j]; v[j] = v[j + 1]; v[j + 1] = tmp; }
    out[t] = v[2];
}

// ---------------------------------------------------------------------------
extern "C" void kernel_launch(void* const* d_in, const int* in_sizes, int n_in,
                              void* d_out, int out_size) {
    const float* audio = (const float*)d_in[0];
    const int n = in_sizes[0];
    const int T = n / HOPLEN + 1;
    float* out = (float*)d_out;

    twiddle_init_kernel<<<8, 256>>>();
    fused_kernel<<<T, 256>>>(audio, n);
    median_kernel<<<(T + 255) / 256, 256>>>(out, T);
}

// round 5
// speedup vs baseline: 3.4518x; 1.1236x over previous
#include <cuda_runtime.h>
#include <math.h>

#define HOPLEN 256
#define NBINS  1025
#define MAXT   8193
#define NLAG   511
#define NC     1024

__device__ float  g_f0[MAXT];
__device__ float2 g_twm[2 * NC];   // twm[j] = exp(-i*pi*j/1024)

__device__ __forceinline__ float2 cmul(float2 a, float2 b) {
    return make_float2(a.x * b.x - a.y * b.y, a.x * b.y + a.y * b.x);
}
__device__ __forceinline__ int swz(int i) { return i ^ ((i >> 4) & 15); }

__global__ void twiddle_init_kernel() {
    int j = blockIdx.x * blockDim.x + threadIdx.x;
    if (j < 2 * NC) {
        float s, c;
        sincospif(-(float)j * (1.0f / 1024.0f), &s, &c);
        g_twm[j] = make_float2(c, s);
    }
}

// packed input point x of the real-packed FFT: audio[start+2x]*hann + i*odd
__device__ __forceinline__ float2 load_pt(const float* __restrict__ audio, int n,
                                          int start, const float2* __restrict__ twm,
                                          int x) {
    int j0 = 2 * x;
    int i0 = start + j0, i1 = i0 + 1;
    if (i0 < 0) i0 = -i0; else if (i0 >= n) i0 = 2 * n - 2 - i0;
    if (i1 < 0) i1 = -i1; else if (i1 >= n) i1 = 2 * n - 2 - i1;
    float4 tv = *(const float4*)(twm + j0);     // (twm[j0], twm[j0+1])
    return make_float2(audio[i0] * (0.5f - 0.5f * tv.x),
                       audio[i1] * (0.5f - 0.5f * tv.z));
}

__device__ __forceinline__ void bfly4(float2 a0, float2 a1, float2 a2, float2 a3,
                                      float2& y0, float2& y1, float2& y2, float2& y3) {
    float2 s02 = make_float2(a0.x + a2.x, a0.y + a2.y);
    float2 d02 = make_float2(a0.x - a2.x, a0.y - a2.y);
    float2 s13 = make_float2(a1.x + a3.x, a1.y + a3.y);
    float2 d13 = make_float2(a1.x - a3.x, a1.y - a3.y);
    y0 = make_float2(s02.x + s13.x, s02.y + s13.y);
    y2 = make_float2(s02.x - s13.x, s02.y - s13.y);
    y1 = make_float2(d02.x + d13.y, d02.y - d13.x);   // d02 - i*d13
    y3 = make_float2(d02.x - d13.y, d02.y + d13.x);   // d02 + i*d13
}

// Merged radix-16 pass (stages S and 4S), thread c in [0,64).
template<int S, bool SWIN, bool SWOUT>
__device__ __forceinline__ void fft_pass16(const float2* __restrict__ src,
                                           float2* __restrict__ dst,
                                           const float2* __restrict__ twm, int c) {
    const int q = c & (S - 1);
    float2 t[4][4];
    #pragma unroll
    for (int j = 0; j < 4; ++j) {
        const int b = c + 64 * j;
        float2 a0 = src[SWIN ? swz(b)       : (b)];
        float2 a1 = src[SWIN ? swz(b + 256) : (b + 256)];
        float2 a2 = src[SWIN ? swz(b + 512) : (b + 512)];
        float2 a3 = src[SWIN ? swz(b + 768) : (b + 768)];
        float2 y0, y1, y2, y3;
        bfly4(a0, a1, a2, a3, y0, y1, y2, y3);
        const int p = b - q;
        t[j][0] = y0;
        t[j][1] = cmul(twm[2 * p], y1);
        t[j][2] = cmul(twm[4 * p], y2);
        t[j][3] = cmul(twm[6 * p], y3);
    }
    #pragma unroll
    for (int rh = 0; rh < 4; ++rh) {
        const int b4 = 4 * c - 3 * q + S * rh;
        const int q4 = b4 & (4 * S - 1);
        const int p4 = b4 - q4;
        float2 y0, y1, y2, y3;
        bfly4(t[0][rh], t[1][rh], t[2][rh], t[3][rh], y0, y1, y2, y3);
        const int base = 4 * p4 + q4;
        dst[SWOUT ? swz(base)          : (base)]          = y0;
        dst[SWOUT ? swz(base + 4 * S)  : (base + 4 * S)]  = cmul(twm[2 * p4], y1);
        dst[SWOUT ? swz(base + 8 * S)  : (base + 8 * S)]  = cmul(twm[4 * p4], y2);
        dst[SWOUT ? swz(base + 12 * S) : (base + 12 * S)] = cmul(twm[6 * p4], y3);
    }
}

// pass1 with inline global load (stage A inputs computed from audio directly)
__device__ __forceinline__ void fft_pass16_load(const float* __restrict__ audio, int n,
                                                int start, float2* __restrict__ dst,
                                                const float2* __restrict__ twm, int c) {
    float2 t[4][4];
    #pragma unroll
    for (int j = 0; j < 4; ++j) {
        const int b = c + 64 * j;
        float2 a0 = load_pt(audio, n, start, twm, b);
        float2 a1 = load_pt(audio, n, start, twm, b + 256);
        float2 a2 = load_pt(audio, n, start, twm, b + 512);
        float2 a3 = load_pt(audio, n, start, twm, b + 768);
        float2 y0, y1, y2, y3;
        bfly4(a0, a1, a2, a3, y0, y1, y2, y3);
        t[j][0] = y0;                              // S=1: q=0, p=b
        t[j][1] = cmul(twm[2 * b], y1);
        t[j][2] = cmul(twm[4 * b], y2);
        t[j][3] = cmul(twm[6 * b], y3);
    }
    #pragma unroll
    for (int rh = 0; rh < 4; ++rh) {               // S=1: b4=4c+rh, q4=rh, p4=4c
        float2 y0, y1, y2, y3;
        bfly4(t[0][rh], t[1][rh], t[2][rh], t[3][rh], y0, y1, y2, y3);
        const int p4 = 4 * c;
        const int base = 4 * p4 + rh;
        dst[swz(base)]      = y0;
        dst[swz(base + 4)]  = cmul(twm[2 * p4], y1);
        dst[swz(base + 8)]  = cmul(twm[4 * p4], y2);
        dst[swz(base + 12)] = cmul(twm[6 * p4], y3);
    }
}

// ---------------------------------------------------------------------------
// Fused kernel: TWO frames per block (256 threads). Per frame: real-packed
// 1024-pt FFT (pass1 w/ inline load, pass2 merged, pass3 radix-4) + untangle
// + autocorrelation (16-lag chunks, 1 warp = 4 lags, early exit).
// ---------------------------------------------------------------------------
__global__ void __launch_bounds__(256) fused_kernel(const float* __restrict__ audio,
                                                    int n, int T) {
    const int tid  = threadIdx.x;
    const int fsel = tid >> 7;            // 0 or 1
    const int tloc = tid & 127;
    const int t    = 2 * blockIdx.x + fsel;
    const bool valid = (t < T);

    __shared__ __align__(16) float2 bufA[2][NC];
    __shared__ __align__(16) float2 bufB[2][NC];
    __shared__ __align__(16) float  ac_s[2][516];
    __shared__ int found[2];

    const float2* __restrict__ twm = g_twm;
    const int start = t * HOPLEN - 1024;

    if (tloc == 0) { found[fsel] = valid ? 0 : 1; ac_s[fsel][512] = 0.0f; }

    // ---- FFT pass1: inline load -> bufB (swizzled). 64 threads per frame ----
    if (valid && tloc < 64)
        fft_pass16_load(audio, n, start, bufB[fsel], twm, tloc);
    __syncthreads();
    // ---- pass2 (S=16): bufB(swz) -> bufA ------------------------------------
    if (valid && tloc < 64)
        fft_pass16<16, true, false>(bufB[fsel], bufA[fsel], twm, tloc);
    __syncthreads();
    // ---- pass3 (s=256, twiddle-free): bufA -> bufB, 2 butterflies/thread ----
    if (valid) {
        #pragma unroll
        for (int r = 0; r < 2; ++r) {
            const int b = tloc + 128 * r;
            float2 y0, y1, y2, y3;
            bfly4(bufA[fsel][b], bufA[fsel][b + 256],
                  bufA[fsel][b + 512], bufA[fsel][b + 768], y0, y1, y2, y3);
            bufB[fsel][b]       = y0;
            bufB[fsel][b + 256] = y1;
            bufB[fsel][b + 512] = y2;
            bufB[fsel][b + 768] = y3;
        }
    }
    __syncthreads();

    // ---- untangle rfft, magnitude into m (= bufA[fsel] as floats) -----------
    float* m = (float*)bufA[fsel];
    if (valid) {
        const float2* Z = bufB[fsel];
        #pragma unroll
        for (int i = 0; i < 9; ++i) {
            const int k = tloc + 128 * i;
            if (k < NBINS) {
                float2 Zk  = Z[k & (NC - 1)];
                float2 Zmk = Z[(NC - k) & (NC - 1)];
                float Er = 0.5f * (Zk.x + Zmk.x);
                float Ei = 0.5f * (Zk.y - Zmk.y);
                float u  = Zk.x - Zmk.x;
                float v  = Zk.y + Zmk.y;
                float2 W = twm[k];
                float Xr = Er + 0.5f * (W.x * v + W.y * u);
                float Xi = Ei + 0.5f * (W.y * v - W.x * u);
                m[k] = sqrtf(Xr * Xr + Xi * Xi);
            }
        }
        for (int i = NBINS + tloc; i < 2048; i += 128) m[i] = 0.0f;
    }
    __syncthreads();

    // ---- autocorrelation: 16-lag chunks, warp = 4 lags, early exit ----------
    const int w_f  = (tid >> 5) & 3;       // warp within frame: lag group
    const int lane = tid & 31;
    const int kbase = 4 * lane;

    float4 areg[9];
    if (valid) {
        #pragma unroll
        for (int i = 0; i < 9; ++i)
            areg[i] = *(const float4*)(m + kbase + 128 * i);
    }

    int loLag = 2;
    #pragma unroll 1
    for (int C = 0; C <= 496; C += 16) {
        if (!found[fsel]) {
            const int L = C + 4 * w_f;
            float4 acc = make_float4(0.f, 0.f, 0.f, 0.f);
            #pragma unroll
            for (int i = 0; i < 9; ++i) {
                const float4 a = areg[i];
                const float* bp = m + kbase + 128 * i + L;
                float4 b0 = *(const float4*)bp;
                float4 b1 = *(const float4*)(bp + 4);
                acc.x += a.x * b0.x + a.y * b0.y + a.z * b0.z + a.w * b0.w;
                acc.y += a.x * b0.y + a.y * b0.z + a.z * b0.w + a.w * b1.x;
                acc.z += a.x * b0.z + a.y * b0.w + a.z * b1.x + a.w * b1.y;
                acc.w += a.x * b0.w + a.y * b1.x + a.z * b1.y + a.w * b1.z;
            }
            #pragma unroll
            for (int mask = 1; mask < 32; mask <<= 1) {
                acc.x += __shfl_xor_sync(0xffffffffu, acc.x, mask);
                acc.y += __shfl_xor_sync(0xffffffffu, acc.y, mask);
                acc.z += __shfl_xor_sync(0xffffffffu, acc.z, mask);
                acc.w += __shfl_xor_sync(0xffffffffu, acc.w, mask);
            }
            if (lane == 0) *(float4*)&ac_s[fsel][L] = acc;
        }
        __syncthreads();

        const int hiLag   = C + 15;
        const int checkHi = (hiLag >= NLAG) ? NLAG : (hiLag - 1);
        if (tloc < 32 && !found[fsel]) {
            const int lam = loLag + tloc;
            if (lam <= checkHi) {
                float vm = ac_s[fsel][lam - 1];
                float v0 = ac_s[fsel][lam];
                float vp = ac_s[fsel][lam + 1];
                if (v0 > vm && v0 > vp) found[fsel] = 1;
            }
        }
        loLag = checkHi + 1;
        __syncthreads();
        if (found[0] && found[1]) break;   // uniform after barrier
    }

    if (valid && tloc == 0) g_f0[t] = found[fsel] ? 50.0f : 0.0f;
}

// ---------------------------------------------------------------------------
__global__ void median_kernel(float* __restrict__ out, int T) {
    int t = blockIdx.x * blockDim.x + threadIdx.x;
    if (t >= T) return;
    float v[5];
    #pragma unroll
    for (int i = 0; i < 5; ++i) {
        int j = t - 2 + i;
        j = max(0, min(T - 1, j));
        v[i] = g_f0[j];
    }
    #pragma unroll
    for (int i = 0; i < 4; ++i)
        #pragma unroll
        for (int j = 0; j < 4 - i; ++j)
            if (v[j] > v[j + 1]) { float tmp = v[j]; v[j] = v[j + 1]; v[j + 1] = tmp; }
    out[t] = v[2];
}

// ---------------------------------------------------------------------------
extern "C" void kernel_launch(void* const* d_in, const int* in_sizes, int n_in,
                              void* d_out, int out_size) {
    const float* audio = (const float*)d_in[0];
    const int n = in_sizes[0];
    const int T = n / HOPLEN + 1;
    float* out = (float*)d_out;

    twiddle_init_kernel<<<8, 256>>>();
    fused_kernel<<<(T + 1) / 2, 256>>>(audio, n, T);
    median_kernel<<<(T + 255) / 256, 256>>>(out, T);
}

// round 7
// speedup vs baseline: 3.7924x; 1.0987x over previous
#include <cuda_runtime.h>
#include <math.h>

#define HOPLEN 256
#define NBINS  1025
#define MAXT   8193
#define NLAG   511
#define NC     1024

__device__ float g_f0[MAXT];

// ---------------------------------------------------------------------------
// Compile-time twiddle table: twm[j] = exp(-i*pi*j/1024), j in [0,2048).
// Octant-reduced Taylor in double (error < 1e-19), rounded to float.
// ---------------------------------------------------------------------------
struct alignas(16) TwTab { float2 v[2048]; };

constexpr double tp_sin(double x) {
    double t = x, s = x;
    for (int k = 1; k <= 10; ++k) { t = -t * x * x / ((2.0 * k) * (2.0 * k + 1.0)); s += t; }
    return s;
}
constexpr double tp_cos(double x) {
    double t = 1.0, s = 1.0;
    for (int k = 1; k <= 10; ++k) { t = -t * x * x / ((2.0 * k - 1.0) * (2.0 * k)); s += t; }
    return s;
}
constexpr TwTab make_twtab() {
    TwTab tab{};
    const double PI = 3.14159265358979323846264338327950288;
    for (int j = 0; j < 2048; ++j) {
        int q = (j >> 9) & 3;          // quadrant of theta = pi*j/1024
        int r = j & 511;
        double c = 0.0, s = 0.0;       // cos/sin of phi = pi*r/1024
        if (r <= 256) { double x = PI * r / 1024.0;         c = tp_cos(x); s = tp_sin(x); }
        else          { double x = PI * (512 - r) / 1024.0; c = tp_sin(x); s = tp_cos(x); }
        double ct = 0.0, st = 0.0;
        switch (q) {
            case 0:  ct = c;  st = s;  break;
            case 1:  ct = -s; st = c;  break;
            case 2:  ct = -c; st = -s; break;
            default: ct = s;  st = -c; break;
        }
        tab.v[j].x = (float)ct;
        tab.v[j].y = (float)(-st);     // exp(-i*theta)
    }
    return tab;
}
__device__ constexpr TwTab g_twc = make_twtab();

__device__ __forceinline__ float2 cmul(float2 a, float2 b) {
    return make_float2(a.x * b.x - a.y * b.y, a.x * b.y + a.y * b.x);
}
__device__ __forceinline__ int swz(int i) { return i ^ ((i >> 4) & 15); }

// packed input point x: audio[start+2x]*hann + i * audio[start+2x+1]*hann
__device__ __forceinline__ float2 load_pt(const float* __restrict__ audio, int n,
                                          int start, const float2* __restrict__ twm,
                                          int x) {
    int j0 = 2 * x;
    int i0 = start + j0, i1 = i0 + 1;
    if (i0 < 0) i0 = -i0; else if (i0 >= n) i0 = 2 * n - 2 - i0;
    if (i1 < 0) i1 = -i1; else if (i1 >= n) i1 = 2 * n - 2 - i1;
    float4 tv = *(const float4*)(twm + j0);
    return make_float2(audio[i0] * (0.5f - 0.5f * tv.x),
                       audio[i1] * (0.5f - 0.5f * tv.z));
}

__device__ __forceinline__ void bfly4(float2 a0, float2 a1, float2 a2, float2 a3,
                                      float2& y0, float2& y1, float2& y2, float2& y3) {
    float2 s02 = make_float2(a0.x + a2.x, a0.y + a2.y);
    float2 d02 = make_float2(a0.x - a2.x, a0.y - a2.y);
    float2 s13 = make_float2(a1.x + a3.x, a1.y + a3.y);
    float2 d13 = make_float2(a1.x - a3.x, a1.y - a3.y);
    y0 = make_float2(s02.x + s13.x, s02.y + s13.y);
    y2 = make_float2(s02.x - s13.x, s02.y - s13.y);
    y1 = make_float2(d02.x + d13.y, d02.y - d13.x);
    y3 = make_float2(d02.x - d13.y, d02.y + d13.x);
}

// Merged radix-16 pass (stages S and 4S), thread c in [0,64).
template<int S, bool SWIN, bool SWOUT>
__device__ __forceinline__ void fft_pass16(const float2* __restrict__ src,
                                           float2* __restrict__ dst,
                                           const float2* __restrict__ twm, int c) {
    const int q = c & (S - 1);
    float2 t[4][4];
    #pragma unroll
    for (int j = 0; j < 4; ++j) {
        const int b = c + 64 * j;
        float2 a0 = src[SWIN ? swz(b)       : (b)];
        float2 a1 = src[SWIN ? swz(b + 256) : (b + 256)];
        float2 a2 = src[SWIN ? swz(b + 512) : (b + 512)];
        float2 a3 = src[SWIN ? swz(b + 768) : (b + 768)];
        float2 y0, y1, y2, y3;
        bfly4(a0, a1, a2, a3, y0, y1, y2, y3);
        const int p = b - q;
        t[j][0] = y0;
        t[j][1] = cmul(twm[2 * p], y1);
        t[j][2] = cmul(twm[4 * p], y2);
        t[j][3] = cmul(twm[6 * p], y3);
    }
    #pragma unroll
    for (int rh = 0; rh < 4; ++rh) {
        const int b4 = 4 * c - 3 * q + S * rh;
        const int q4 = b4 & (4 * S - 1);
        const int p4 = b4 - q4;
        float2 y0, y1, y2, y3;
        bfly4(t[0][rh], t[1][rh], t[2][rh], t[3][rh], y0, y1, y2, y3);
        const int base = 4 * p4 + q4;
        dst[SWOUT ? swz(base)          : (base)]          = y0;
        dst[SWOUT ? swz(base + 4 * S)  : (base + 4 * S)]  = cmul(twm[2 * p4], y1);
        dst[SWOUT ? swz(base + 8 * S)  : (base + 8 * S)]  = cmul(twm[4 * p4], y2);
        dst[SWOUT ? swz(base + 12 * S) : (base + 12 * S)] = cmul(twm[6 * p4], y3);
    }
}

// pass1 with inline global load (S=1 specialization)
__device__ __forceinline__ void fft_pass16_load(const float* __restrict__ audio, int n,
                                                int start, float2* __restrict__ dst,
                                                const float2* __restrict__ twm, int c) {
    float2 t[4][4];
    #pragma unroll
    for (int j = 0; j < 4; ++j) {
        const int b = c + 64 * j;
        float2 a0 = load_pt(audio, n, start, twm, b);
        float2 a1 = load_pt(audio, n, start, twm, b + 256);
        float2 a2 = load_pt(audio, n, start, twm, b + 512);
        float2 a3 = load_pt(audio, n, start, twm, b + 768);
        float2 y0, y1, y2, y3;
        bfly4(a0, a1, a2, a3, y0, y1, y2, y3);
        t[j][0] = y0;
        t[j][1] = cmul(twm[2 * b], y1);
        t[j][2] = cmul(twm[4 * b], y2);
        t[j][3] = cmul(twm[6 * b], y3);
    }
    #pragma unroll
    for (int rh = 0; rh < 4; ++rh) {
        float2 y0, y1, y2, y3;
        bfly4(t[0][rh], t[1][rh], t[2][rh], t[3][rh], y0, y1, y2, y3);
        const int p4 = 4 * c;
        const int base = 4 * p4 + rh;
        dst[swz(base)]      = y0;
        dst[swz(base + 4)]  = cmul(twm[2 * p4], y1);
        dst[swz(base + 8)]  = cmul(twm[4 * p4], y2);
        dst[swz(base + 12)] = cmul(twm[6 * p4], y3);
    }
}

// magnitude of bins k and 1024-k from Z[k], Z[1024-k], W = twm[k]
__device__ __forceinline__ void pairmag(float2 Zk, float2 Zm, float2 W,
                                        float& mk, float& mp) {
    float Er = 0.5f * (Zk.x + Zm.x);
    float Ei = 0.5f * (Zk.y - Zm.y);
    float u  = Zk.x - Zm.x;
    float v  = Zk.y + Zm.y;
    float P  = 0.5f * (W.x * v + W.y * u);
    float Q  = 0.5f * (W.y * v - W.x * u);
    float ar = Er + P, ai = Ei + Q;
    float br = Er - P, bi = Q - Ei;
    mk = sqrtf(ar * ar + ai * ai);
    mp = sqrtf(br * br + bi * bi);
}

// ---------------------------------------------------------------------------
// Fused kernel: TWO frames per block (256 threads).
// pass1(load) -> pass2 -> merged pass3+untangle (register conjugate pairs)
// -> autocorrelation (16-lag chunks, 9-shfl reduction, early exit).
// ---------------------------------------------------------------------------
__global__ void __launch_bounds__(256) fused_kernel(const float* __restrict__ audio,
                                                    int n, int T) {
    const int tid  = threadIdx.x;
    const int fsel = tid >> 7;
    const int tloc = tid & 127;
    const int t    = 2 * blockIdx.x + fsel;
    const bool valid = (t < T);

    __shared__ __align__(16) float2 bufA[2][NC];
    __shared__ __align__(16) float2 bufB[2][NC];
    __shared__ __align__(16) float  ac_s[2][516];
    __shared__ int found[2];

    const float2* __restrict__ twm = g_twc.v;
    const int start = t * HOPLEN - 1024;

    if (tloc == 0) { found[fsel] = valid ? 0 : 1; ac_s[fsel][512] = 0.0f; }

    // ---- pass1 (S=1,4): inline load -> bufB (swizzled); 64 threads/frame ----
    if (valid && tloc < 64)
        fft_pass16_load(audio, n, start, bufB[fsel], twm, tloc);
    __syncthreads();
    // ---- pass2 (S=16,64): bufB(swz) -> bufA ---------------------------------
    if (valid && tloc < 64)
        fft_pass16<16, true, false>(bufB[fsel], bufA[fsel], twm, tloc);
    __syncthreads();

    // ---- merged pass3 (s=256) + rfft untangle + magnitude -> m (= bufB) -----
    float* m = (float*)bufB[fsel];
    if (valid) {
        const int j  = tloc;
        const int b2 = (j == 0) ? 128 : (256 - j);
        const float2* A = bufA[fsel];
        float2 Z1[4], Z2[4];
        bfly4(A[j],  A[j + 256],  A[j + 512],  A[j + 768],
              Z1[0], Z1[1], Z1[2], Z1[3]);
        bfly4(A[b2], A[b2 + 256], A[b2 + 512], A[b2 + 768],
              Z2[0], Z2[1], Z2[2], Z2[3]);
        if (j > 0) {
            pairmag(Z1[0], Z2[3], twm[j],       m[j],       m[1024 - j]);
            pairmag(Z1[1], Z2[2], twm[j + 256], m[j + 256], m[768 - j]);
            pairmag(Z2[1], Z1[2], twm[512 - j], m[512 - j], m[512 + j]);
            pairmag(Z2[0], Z1[3], twm[256 - j], m[256 - j], m[768 + j]);
        } else {
            float dummy;
            pairmag(Z1[0], Z1[0], twm[0],   m[0],   m[1024]);
            pairmag(Z1[1], Z1[3], twm[256], m[256], m[768]);
            pairmag(Z1[2], Z1[2], twm[512], m[512], dummy);
            pairmag(Z2[0], Z2[3], twm[128], m[128], m[896]);
            pairmag(Z2[1], Z2[2], twm[384], m[384], m[640]);
        }
        for (int i = NBINS + tloc; i < 2048; i += 128) m[i] = 0.0f;
    }
    __syncthreads();

    // ---- autocorrelation: 16-lag chunks, warp = 4 lags, early exit ----------
    const int w_f  = (tid >> 5) & 3;
    const int lane = tid & 31;
    const int kbase = 4 * lane;

    float4 areg[9];
    if (valid) {
        #pragma unroll
        for (int i = 0; i < 9; ++i)
            areg[i] = *(const float4*)(m + kbase + 128 * i);
    }

    int loLag = 2;
    #pragma unroll 1
    for (int C = 0; C <= 496; C += 16) {
        if (!found[fsel]) {
            const int L = C + 4 * w_f;
            float4 acc = make_float4(0.f, 0.f, 0.f, 0.f);
            #pragma unroll
            for (int i = 0; i < 9; ++i) {
                const float4 a = areg[i];
                const float* bp = m + kbase + 128 * i + L;
                float4 b0 = *(const float4*)bp;
                float4 b1 = *(const float4*)(bp + 4);
                acc.x += a.x * b0.x + a.y * b0.y + a.z * b0.z + a.w * b0.w;
                acc.y += a.x * b0.y + a.y * b0.z + a.z * b0.w + a.w * b1.x;
                acc.z += a.x * b0.z + a.y * b0.w + a.z * b1.x + a.w * b1.y;
                acc.w += a.x * b0.w + a.y * b1.x + a.z * b1.y + a.w * b1.z;
            }
            // 4-sum warp reduction in 9 shuffles
            float pa, pb;
            {
                float ox = __shfl_xor_sync(0xffffffffu, acc.x, 1);
                float oy = __shfl_xor_sync(0xffffffffu, acc.y, 1);
                float oz = __shfl_xor_sync(0xffffffffu, acc.z, 1);
                float ow = __shfl_xor_sync(0xffffffffu, acc.w, 1);
                bool odd = (lane & 1);
                pa = odd ? (acc.y + oy) : (acc.x + ox);
                pb = odd ? (acc.w + ow) : (acc.z + oz);
            }
            pa += __shfl_xor_sync(0xffffffffu, pa, 2);
            pb += __shfl_xor_sync(0xffffffffu, pb, 2);
            float val = (lane & 2) ? pb : pa;
            val += __shfl_xor_sync(0xffffffffu, val, 4);
            val += __shfl_xor_sync(0xffffffffu, val, 8);
            val += __shfl_xor_sync(0xffffffffu, val, 16);
            if (lane < 4) ac_s[fsel][L + lane] = val;
        }
        __syncthreads();

        const int hiLag   = C + 15;
        const int checkHi = (hiLag >= NLAG) ? NLAG : (hiLag - 1);
        if (tloc < 32 && !found[fsel]) {
            const int lam = loLag + tloc;
            if (lam <= checkHi) {
                float vm = ac_s[fsel][lam - 1];
                float v0 = ac_s[fsel][lam];
                float vp = ac_s[fsel][lam + 1];
                if (v0 > vm && v0 > vp) found[fsel] = 1;
            }
        }
        loLag = checkHi + 1;
        __syncthreads();
        if (found[0] && found[1]) break;   // uniform after barrier
    }

    if (valid && tloc == 0) g_f0[t] = found[fsel] ? 50.0f : 0.0f;
}

// ---------------------------------------------------------------------------
__global__ void median_kernel(float* __restrict__ out, int T) {
    int t = blockIdx.x * blockDim.x + threadIdx.x;
    if (t >= T) return;
    float v[5];
    #pragma unroll
    for (int i = 0; i < 5; ++i) {
        int j = t - 2 + i;
        j = max(0, min(T - 1, j));
        v[i] = g_f0[j];
    }
    #pragma unroll
    for (int i = 0; i < 4; ++i)
        #pragma unroll
        for (int j = 0; j < 4 - i; ++j)
            if (v[j] > v[j + 1]) { float tmp = v[j]; v[j] = v[j + 1]; v[j + 1] = tmp; }
    out[t] = v[2];
}

// ---------------------------------------------------------------------------
extern "C" void kernel_launch(void* const* d_in, const int* in_sizes, int n_in,
                              void* d_out, int out_size) {
    const float* audio = (const float*)d_in[0];
    const int n = in_sizes[0];
    const int T = n / HOPLEN + 1;
    float* out = (float*)d_out;

    fused_kernel<<<(T + 1) / 2, 256>>>(audio, n, T);
    median_kernel<<<(T + 255) / 256, 256>>>(out, T);
}